// round 11
// baseline (speedup 1.0000x reference)
#include <cuda_runtime.h>

// Problem shape (fixed by the dataset):
//   z:      (4096, 1, 64, 128) f32  -> row of 8192 floats per batch entry
//   ch_ids: (4096,) int32 or int64, values in [0, 32)
//   out:    (4096, 128, 128) f32    -> first 8192 = z row, last 8192 = channel mean
#define BATCH   4096
#define NCH     32
#define ZROW    8192u
#define OROW    16384u
#define NTHR    256                    // 4 row-groups x 64 lanes
#define NGRP    4
#define LANES   64
#define CHUNK   256u                   // floats per tile slice (64 lanes * float4)
#define NCHUNK  32                     // ZROW / CHUNK
#define NTILE   (NCHUNK * NCH)         // 1024
#define NBLK    608                    // 4 persistent blocks per SM (152 SMs)

// ---------------------------------------------------------------------------
// Build the row list for channel c: 8 warps scan all 4096 ids (prefetched to
// registers, 16 ballot rounds each). Two passes (count, then rank+scatter).
// Fixed (warp, round, lane) order -> deterministic. rows[] is ushort.
// ---------------------------------------------------------------------------
__device__ __forceinline__ int build_rows_full(const int* __restrict__ ids32,
                                               int c, int stride,
                                               unsigned short* rows, int tid,
                                               int* segcnt, int* segoff) {
    const int lane = tid & 31;
    const int w    = tid >> 5;                 // 8 warps

    const int base = w * 512;                  // warp covers 512 ids
    int myid[16];
    #pragma unroll
    for (int r = 0; r < 16; ++r)
        myid[r] = ids32[(base + r * 32 + lane) * stride];

    // pass 1: count only
    int count = 0;
    #pragma unroll
    for (int r = 0; r < 16; ++r)
        count += __popc(__ballot_sync(0xffffffffu, myid[r] == c));
    if (lane == 0) segcnt[w] = count;
    __syncthreads();

    if (w == 0) {                              // prefix over 8 warp-segments
        int v = (lane < 8) ? segcnt[lane] : 0;
        int incl = v;
        #pragma unroll
        for (int d = 1; d < 8; d <<= 1) {
            const int t = __shfl_up_sync(0xffffffffu, incl, d);
            if (lane >= d) incl += t;
        }
        if (lane < 8) segoff[lane] = incl - v;
        if (lane == 7) segcnt[8] = incl;
    }
    __syncthreads();

    // pass 2: recompute ballots, scatter
    int pos = segoff[w];
    #pragma unroll
    for (int r = 0; r < 16; ++r) {
        const unsigned mk = __ballot_sync(0xffffffffu, myid[r] == c);
        if (myid[r] == c)
            rows[pos + __popc(mk & ((1u << lane) - 1u))] =
                (unsigned short)(base + r * 32 + lane);
        pos += __popc(mk);
    }
    const int total = segcnt[8];
    __syncthreads();
    return total;
}

// ---------------------------------------------------------------------------
// Persistent fused kernel. 608 blocks x 256 thr; each loops over the 1024
// (chunk, c) tiles grid-stride. Group g (64 lanes) handles rows g, g+4, ...
// of channel c within the tile's 256-float slice:
//   phase 2: unroll-8 batched copy (8 LDG.128 in flight), accumulate
//   phase 3: smem reduce across 4 groups (fixed order) -> channel mean
//   phase 4: write bottom-half mean slice for the same rows
// ---------------------------------------------------------------------------
__global__ void __launch_bounds__(NTHR)
mix_kernel(const float* __restrict__ z, float* __restrict__ out,
           const int* __restrict__ ids) {
    __shared__ unsigned short rows[BATCH];     // 8 KB
    __shared__ float4 red[NGRP][LANES];        // 4 KB cross-group reduce
    __shared__ int    segcnt[9];
    __shared__ int    segoff[8];

    const int tid  = threadIdx.x;
    const int lane = tid & 31;

    // dtype probe once: ch_ids may be int32 or int64 (JAX x64 flag).
    // Interpret as int32[]; first 128 odd words all zero -> int64 (ids < 32).
    int stride;
    {
        const int x = ids[2 * lane + 1] | ids[2 * (lane + 32) + 1] |
                      ids[2 * (lane + 64) + 1] | ids[2 * (lane + 96) + 1];
        const unsigned nz = __ballot_sync(0xffffffffu, x != 0);
        stride = (nz == 0) ? 2 : 1;
    }

    const int g = tid >> 6;                    // row-group 0..3
    const int l = tid & 63;                    // lane within group

    for (int tile = blockIdx.x; tile < NTILE; tile += NBLK) {
        const int c     = tile >> 5;           // 0..31
        const int chunk = tile & 31;           // 0..31

        const int m = build_rows_full(ids, c, stride, rows, tid, segcnt, segoff);

        const unsigned off = (unsigned)chunk * CHUNK + (unsigned)l * 4u;

        // phase 2: copy + partial accumulate (rows g, g+4, ...), 8-deep batch
        const int nb = (m > g) ? (m - g + NGRP - 1) / NGRP : 0;
        float4 acc = make_float4(0.f, 0.f, 0.f, 0.f);
        int j = 0;
        for (; j + 8 <= nb; j += 8) {
            unsigned b[8];
            #pragma unroll
            for (int r = 0; r < 8; ++r) b[r] = rows[g + NGRP * (j + r)];

            float4 v[8];
            #pragma unroll
            for (int r = 0; r < 8; ++r)        // 8 LDG.128 batched in flight
                v[r] = *(const float4*)(z + b[r] * ZROW + off);

            #pragma unroll
            for (int r = 0; r < 8; ++r)
                *(float4*)(out + b[r] * OROW + off) = v[r];

            #pragma unroll
            for (int r = 0; r < 8; ++r) {
                acc.x += v[r].x; acc.y += v[r].y;
                acc.z += v[r].z; acc.w += v[r].w;
            }
        }
        for (; j < nb; ++j) {
            const unsigned b = rows[g + NGRP * j];
            const float4 v = *(const float4*)(z + b * ZROW + off);
            *(float4*)(out + b * OROW + off) = v;
            acc.x += v.x; acc.y += v.y; acc.z += v.z; acc.w += v.w;
        }

        // phase 3: cross-group reduce (deterministic fixed order)
        red[g][l] = acc;
        __syncthreads();
        const float4 p0 = red[0][l];
        const float4 p1 = red[1][l];
        const float4 p2 = red[2][l];
        const float4 p3 = red[3][l];
        const float inv = 1.0f / (float)(m > 0 ? m : 1);
        float4 mn;
        mn.x = ((p0.x + p1.x) + (p2.x + p3.x)) * inv;
        mn.y = ((p0.y + p1.y) + (p2.y + p3.y)) * inv;
        mn.z = ((p0.z + p1.z) + (p2.z + p3.z)) * inv;
        mn.w = ((p0.w + p1.w) + (p2.w + p3.w)) * inv;

        // phase 4: broadcast mean slice to bottom half of the same rows
        j = 0;
        for (; j + 8 <= nb; j += 8) {
            #pragma unroll
            for (int r = 0; r < 8; ++r) {
                const unsigned b = rows[g + NGRP * (j + r)];
                *(float4*)(out + b * OROW + ZROW + off) = mn;
            }
        }
        for (; j < nb; ++j) {
            const unsigned b = rows[g + NGRP * j];
            *(float4*)(out + b * OROW + ZROW + off) = mn;
        }
        __syncthreads();   // protect rows/red before next tile's rebuild
    }
}

extern "C" void kernel_launch(void* const* d_in, const int* in_sizes, int n_in,
                              void* d_out, int out_size) {
    const float* z   = (const float*)d_in[0];
    const int*   ids = (const int*)d_in[1];
    float*       out = (float*)d_out;

    mix_kernel<<<NBLK, NTHR>>>(z, out, ids);
}

// round 13
// speedup vs baseline: 1.0539x; 1.0539x over previous
#include <cuda_runtime.h>

// Problem shape (fixed by the dataset):
//   z:      (4096, 1, 64, 128) f32  -> row of 8192 floats per batch entry
//   ch_ids: (4096,) int32 or int64, values in [0, 32)
//   out:    (4096, 128, 128) f32    -> first 8192 = z row, last 8192 = channel mean
#define BATCH   4096
#define NCH     32
#define ZROW    8192u
#define OROW    16384u
#define NTHR    256                    // 2 row-groups x 128 lanes
#define NGRP    2
#define CHUNK   512u                   // floats per block slice (128 lanes * float4)
#define NCHUNK  16                     // ZROW / CHUNK

// ---------------------------------------------------------------------------
// Build the row list for channel c: 8 warps scan all 4096 ids (prefetched to
// registers, 16 ballot rounds each). Two passes (count, then rank+scatter).
// Fixed (warp, round, lane) order -> deterministic. rows[] is ushort.
// dtype probe: ch_ids may be int32 or int64 (JAX x64 flag). Interpret as
// int32[]; if the first 128 odd words are all zero it's int64 (values < 32).
// ---------------------------------------------------------------------------
__device__ __forceinline__ int build_rows_full(const int* __restrict__ ids32,
                                               int c, unsigned short* rows,
                                               int tid) {
    __shared__ int segcnt[9];
    __shared__ int segoff[8];

    const int lane = tid & 31;
    const int w    = tid >> 5;                 // 8 warps

    int stride;                                // warp-uniform probe
    {
        const int x = ids32[2 * lane + 1] | ids32[2 * (lane + 32) + 1];
        const unsigned nz = __ballot_sync(0xffffffffu, x != 0);
        stride = (nz == 0) ? 2 : 1;
    }

    const int base = w * 512;                  // warp covers 512 ids
    int myid[16];
    #pragma unroll
    for (int r = 0; r < 16; ++r)
        myid[r] = ids32[(base + r * 32 + lane) * stride];

    // pass 1: count only
    int count = 0;
    #pragma unroll
    for (int r = 0; r < 16; ++r)
        count += __popc(__ballot_sync(0xffffffffu, myid[r] == c));
    if (lane == 0) segcnt[w] = count;
    __syncthreads();

    if (w == 0) {                              // prefix over 8 warp-segments
        int v = (lane < 8) ? segcnt[lane] : 0;
        int incl = v;
        #pragma unroll
        for (int d = 1; d < 8; d <<= 1) {
            const int t = __shfl_up_sync(0xffffffffu, incl, d);
            if (lane >= d) incl += t;
        }
        if (lane < 8) segoff[lane] = incl - v;
        if (lane == 7) segcnt[8] = incl;
    }
    __syncthreads();

    // pass 2: recompute ballots, scatter
    int pos = segoff[w];
    #pragma unroll
    for (int r = 0; r < 16; ++r) {
        const unsigned mk = __ballot_sync(0xffffffffu, myid[r] == c);
        if (myid[r] == c)
            rows[pos + __popc(mk & ((1u << lane) - 1u))] =
                (unsigned short)(base + r * 32 + lane);
        pos += __popc(mk);
    }
    const int total = segcnt[8];
    __syncthreads();
    return total;
}

// ---------------------------------------------------------------------------
// Single fused kernel. grid = (NCHUNK, NCH) = 512 blocks, 256 thr, all
// co-resident (6 blocks/SM capacity). Group g (128 lanes) handles rows
// g, g+2, ... of channel c:
//   phase 2: unroll-8 batched copy (8 LDG.128 in flight), streaming stores
//   phase 3: smem reduce across the 2 groups (fixed order) -> channel mean
//   phase 4: streaming-store bottom-half mean slice for the same rows
// ---------------------------------------------------------------------------
__global__ void __launch_bounds__(NTHR)
mix_kernel(const float* __restrict__ z, float* __restrict__ out,
           const int* __restrict__ ids) {
    __shared__ unsigned short rows[BATCH];   // 8 KB
    __shared__ float4 red[NGRP][128];        // 4 KB cross-group reduce

    const int chunk = blockIdx.x;
    const int c     = blockIdx.y;
    const int tid   = threadIdx.x;

    const int m = build_rows_full(ids, c, rows, tid);

    const int      g   = tid >> 7;           // row-group 0..1
    const int      l   = tid & 127;          // lane within group
    const unsigned off = (unsigned)chunk * CHUNK + (unsigned)l * 4u;

    // phase 2: copy + partial accumulate (rows g, g+2, ...), 8-deep batch
    const int nb = (m > g) ? (m - g + NGRP - 1) / NGRP : 0;
    float4 acc = make_float4(0.f, 0.f, 0.f, 0.f);
    int j = 0;
    for (; j + 8 <= nb; j += 8) {
        unsigned b[8];
        #pragma unroll
        for (int r = 0; r < 8; ++r) b[r] = rows[g + NGRP * (j + r)];

        float4 v[8];
        #pragma unroll
        for (int r = 0; r < 8; ++r)          // 8 LDG.128 batched in flight
            v[r] = *(const float4*)(z + b[r] * ZROW + off);

        #pragma unroll
        for (int r = 0; r < 8; ++r)          // evict-first streaming stores
            __stcs((float4*)(out + b[r] * OROW + off), v[r]);

        #pragma unroll
        for (int r = 0; r < 8; ++r) {
            acc.x += v[r].x; acc.y += v[r].y;
            acc.z += v[r].z; acc.w += v[r].w;
        }
    }
    for (; j < nb; ++j) {
        const unsigned b = rows[g + NGRP * j];
        const float4 v = *(const float4*)(z + b * ZROW + off);
        __stcs((float4*)(out + b * OROW + off), v);
        acc.x += v.x; acc.y += v.y; acc.z += v.z; acc.w += v.w;
    }

    // phase 3: cross-group reduce (deterministic fixed order)
    red[g][l] = acc;
    __syncthreads();
    const float4 p0 = red[0][l];
    const float4 p1 = red[1][l];
    const float inv = 1.0f / (float)(m > 0 ? m : 1);
    float4 mn;
    mn.x = (p0.x + p1.x) * inv;
    mn.y = (p0.y + p1.y) * inv;
    mn.z = (p0.z + p1.z) * inv;
    mn.w = (p0.w + p1.w) * inv;

    // phase 4: broadcast mean slice to bottom half of the same rows
    j = 0;
    for (; j + 8 <= nb; j += 8) {
        #pragma unroll
        for (int r = 0; r < 8; ++r) {
            const unsigned b = rows[g + NGRP * (j + r)];
            __stcs((float4*)(out + b * OROW + ZROW + off), mn);
        }
    }
    for (; j < nb; ++j) {
        const unsigned b = rows[g + NGRP * j];
        __stcs((float4*)(out + b * OROW + ZROW + off), mn);
    }
}

extern "C" void kernel_launch(void* const* d_in, const int* in_sizes, int n_in,
                              void* d_out, int out_size) {
    const float* z   = (const float*)d_in[0];
    const int*   ids = (const int*)d_in[1];
    float*       out = (float*)d_out;

    dim3 grid(NCHUNK, NCH);
    mix_kernel<<<grid, NTHR>>>(z, out, ids);
}